// round 1
// baseline (speedup 1.0000x reference)
#include <cuda_runtime.h>
#include <cstdint>
#include <cstddef>

// ---------------------------------------------------------------------------
// Problem constants (from reference)
// ---------------------------------------------------------------------------
#define LOG_GAMMA  0.019802627296179713f   // ln(1.02)
#define ALPHA_     (-1.005033585350145e-05f) // ln(0.99)/1000
#define INIT_LOGW  (-1.3943265389999528f)  // ln(0.248)
#define INIT_LOGP  (-6.907755278982137f)   // ln(0.001)
#define INV_TEMP   (0.001f)                // 1/1000
#define EPS_       (1e-12f)
// Firing impossible once c_t < 2.16e-9 (see analysis); 1e-10 = safe margin.
#define CUT_       (1e-10f)

#define MAXT_CAP 12288
#define NB_CAP   1024

__device__ float g_c[MAXT_CAP];       // c_t = exp(logit_t) - eps
__device__ float g_R[MAXT_CAP + 1];   // exclusive prefix sums of r_t
__device__ int   g_tcut;              // first t with c_t < CUT_
__device__ float g_bsum[NB_CAP];      // per-block partial sums

// ---------------------------------------------------------------------------
// Block-wide exclusive scan, 1024 threads fixed. sh must hold >= 33 floats.
// ---------------------------------------------------------------------------
__device__ __forceinline__ float block_exscan_1024(float v, float* sh) {
    const int lane = threadIdx.x & 31;
    const int wid  = threadIdx.x >> 5;
    float inc = v;
#pragma unroll
    for (int o = 1; o < 32; o <<= 1) {
        float n = __shfl_up_sync(0xffffffffu, inc, o);
        if (lane >= o) inc += n;
    }
    if (lane == 31) sh[wid] = inc;
    __syncthreads();
    if (wid == 0) {
        float wv = sh[lane];
        float wi = wv;
#pragma unroll
        for (int o = 1; o < 32; o <<= 1) {
            float n = __shfl_up_sync(0xffffffffu, wi, o);
            if (lane >= o) wi += n;
        }
        sh[lane] = wi - wv;  // warp-exclusive offsets
    }
    __syncthreads();
    float res = sh[wid] + (inc - v);
    __syncthreads();  // sh reusable by next scan
    return res;
}

// ---------------------------------------------------------------------------
// Kernel A: scalar precompute (one block, 1024 threads).
//   logw_{t+1} = INIT_LOGW + prefix_{<=t} d,  d_t = LOG_GAMMA + log1p(-exp(a_t))
//   logp_t     = INIT_LOGP + prefix_{<t} e,   e_t = ALPHA*exp(a_t)*exp(logw_t)
//   c_t = p/(1-p) - eps,  p = exp(logp_t)
//   r_t = exp(logw_{t+1}/TEMP);  R = exclusive prefix of r; R[T] = total
// ---------------------------------------------------------------------------
__global__ void __launch_bounds__(1024, 1)
precompute_kernel(const float* __restrict__ acts, int T) {
    __shared__ float sh[33];
    const int tid = threadIdx.x;
    if (tid == 0) g_tcut = T;   // reset each launch (barriers below order this
                                // before any atomicMin)
    const int PT = (T + 1023) >> 10;  // elems per thread (<= 12 for T<=12288)
    const int i0 = tid * PT;

    float a[12], dpre[12], dval[12];
    float run = 0.f;
#pragma unroll
    for (int j = 0; j < 12; j++) {
        if (j >= PT) break;
        int i = i0 + j;
        float av = (i < T) ? acts[i] : -10.f;
        float dj = (i < T) ? (LOG_GAMMA + log1pf(-__expf(av))) : 0.f;
        a[j] = av; dpre[j] = run; dval[j] = dj;
        run += dj;
    }
    float woff = block_exscan_1024(run, sh);

    float epre[12];
    float erun = 0.f;
#pragma unroll
    for (int j = 0; j < 12; j++) {
        if (j >= PT) break;
        int i = i0 + j;
        float ej = 0.f;
        if (i < T) {
            float lwb = INIT_LOGW + woff + dpre[j];      // logw BEFORE step i
            ej = (ALPHA_ * __expf(a[j])) * __expf(lwb);  // may be -inf late; ok
        }
        epre[j] = erun;
        erun += ej;
    }
    float eoff = block_exscan_1024(erun, sh);

    float rpre[12], rval[12];
    float rrun = 0.f;
#pragma unroll
    for (int j = 0; j < 12; j++) {
        if (j >= PT) break;
        int i = i0 + j;
        float rj = 0.f;
        if (i < T) {
            float logp = INIT_LOGP + eoff + epre[j];     // logp BEFORE step i
            float p = __expf(logp);
            float c = __fdividef(p, 1.0f - p) - EPS_;
            g_c[i] = c;
            // NaN-safe: record cutoff when c not >= CUT_ (NaN only occurs far
            // past the real crossing; recording a larger index is harmless).
            if (!(c >= CUT_)) atomicMin(&g_tcut, i);
            float lwa = INIT_LOGW + woff + dpre[j] + dval[j];  // logw AFTER
            rj = __expf(lwa * INV_TEMP);
        }
        rpre[j] = rrun; rval[j] = rj;
        rrun += rj;
    }
    float roff = block_exscan_1024(rrun, sh);
#pragma unroll
    for (int j = 0; j < 12; j++) {
        if (j >= PT) break;
        int i = i0 + j;
        if (i < T) {
            g_R[i] = roff + rpre[j];
            if (i == T - 1) g_R[T] = roff + rpre[j] + rval[j];
        }
    }
}

// ---------------------------------------------------------------------------
// Kernel B: per-batch first-fire search.
// Block = 32 batch elements (lane) x 32 warps over t, unroll 4 -> 128 t/iter.
// fired  <=>  log(u2+eps) > c_t * log(u1+eps)
// ---------------------------------------------------------------------------
__global__ void __launch_bounds__(1024, 1)
mainscan_kernel(const float* __restrict__ u1, const float* __restrict__ u2,
                int T, int BATCH) {
    __shared__ int sh_first[32];
    const int tid  = threadIdx.x;
    const int lane = tid & 31;
    const int w    = tid >> 5;
    const int b    = blockIdx.x * 32 + lane;
    const bool bvalid = (b < BATCH);

    if (tid < 32) sh_first[tid] = T;
    const int tcut = g_tcut;
    __syncthreads();  // sh_first init visible before first all-fired check

    for (int base = 0; base < tcut; base += 128) {
        // Exit when every b in the block has a recorded fire (uniform result).
        // Pre-barrier read of sh_first races only with atomicMin -> benign.
        if (__syncthreads_and(sh_first[lane] < T)) break;

        float x1[4], x2[4], cc[4];
        int   tt[4];
#pragma unroll
        for (int j = 0; j < 4; j++) {
            int t = base + w + 32 * j;
            tt[j] = t;
            bool v = (t < tcut) && bvalid;
            size_t idx = (size_t)t * (size_t)BATCH + (size_t)b;
            x1[j] = v ? __ldg(&u1[idx]) : 0.f;
            x2[j] = v ? __ldg(&u2[idx]) : 0.f;
            cc[j] = (t < tcut) ? g_c[t] : 0.f;
        }
#pragma unroll
        for (int j = 0; j < 4; j++) {
            if (tt[j] < tcut && bvalid) {
                bool fired = __logf(x2[j] + EPS_) > cc[j] * __logf(x1[j] + EPS_);
                if (fired) atomicMin(&sh_first[lane], tt[j]);  // rare
            }
        }
    }
    __syncthreads();

    if (w == 0) {
        float val = bvalid ? g_R[sh_first[lane]] : 0.f;  // R[k_b] (k=T if none)
#pragma unroll
        for (int o = 16; o > 0; o >>= 1)
            val += __shfl_down_sync(0xffffffffu, val, o);
        if (lane == 0) g_bsum[blockIdx.x] = val;
    }
}

// ---------------------------------------------------------------------------
// Kernel C: deterministic final reduction + mean.
// ---------------------------------------------------------------------------
__global__ void __launch_bounds__(128, 1)
reduce_kernel(float* __restrict__ out, int nb, float inv_batch) {
    __shared__ float sh[4];
    const int tid = threadIdx.x;
    float v = 0.f;
    for (int i = tid; i < nb; i += 128) v += g_bsum[i];
#pragma unroll
    for (int o = 16; o > 0; o >>= 1)
        v += __shfl_down_sync(0xffffffffu, v, o);
    if ((tid & 31) == 0) sh[tid >> 5] = v;
    __syncthreads();
    if (tid == 0) {
        float s = sh[0] + sh[1] + sh[2] + sh[3];
        out[0] = s * inv_batch;
    }
}

// ---------------------------------------------------------------------------
extern "C" void kernel_launch(void* const* d_in, const int* in_sizes, int n_in,
                              void* d_out, int out_size) {
    const float* acts = (const float*)d_in[0];
    const float* u1   = (const float*)d_in[1];
    const float* u2   = (const float*)d_in[2];
    int T = in_sizes[0];
    if (T > MAXT_CAP) T = MAXT_CAP;  // defensive; problem shape is T=10000
    int BATCH = in_sizes[1] / in_sizes[0];
    int nb = (BATCH + 31) / 32;
    if (nb > NB_CAP) nb = NB_CAP;

    precompute_kernel<<<1, 1024>>>(acts, T);
    mainscan_kernel<<<nb, 1024>>>(u1, u2, T, BATCH);
    reduce_kernel<<<1, 128>>>((float*)d_out, nb, 1.0f / (float)BATCH);
}